// round 6
// baseline (speedup 1.0000x reference)
#include <cuda_runtime.h>

// Problem constants (fixed by the reference setup_inputs)
#define NROWS   65536
#define DCOLS   1024
#define WARPS_PER_BLOCK 8
#define NBLOCKS (NROWS / WARPS_PER_BLOCK)   // 8192 blocks, 1 row per warp

#define RAD2DEG 57.29577951308232

// Deterministic per-block partials: [0..NBLOCKS) = sum(dot^2),
// [NBLOCKS..2N) = sum(x^2), [2N..3N) = sum(y^2). Fully overwritten every call,
// so kernel_launch stays deterministic across graph replays.
__device__ float g_partials[NBLOCKS * 3];

__global__ __launch_bounds__(256, 4)
void rowdot_kernel(const float* __restrict__ x, const float* __restrict__ y) {
    const int warp = threadIdx.x >> 5;
    const int lane = threadIdx.x & 31;
    const int row  = blockIdx.x * WARPS_PER_BLOCK + warp;

    const float4* __restrict__ xr =
        reinterpret_cast<const float4*>(x + (size_t)row * DCOLS);
    const float4* __restrict__ yr =
        reinterpret_cast<const float4*>(y + (size_t)row * DCOLS);

    float dot = 0.f, sx = 0.f, sy = 0.f;
    // 1024 floats / row = 256 float4; 32 lanes -> 8 iters, fully coalesced.
    // 16 independent LDG.128 per thread -> MLP well above DRAM-latency-hiding
    // threshold (577 cyc @ MLP=1 model).
    #pragma unroll
    for (int i = 0; i < 8; ++i) {
        float4 a = xr[lane + i * 32];
        float4 b = yr[lane + i * 32];
        dot = fmaf(a.x, b.x, dot); dot = fmaf(a.y, b.y, dot);
        dot = fmaf(a.z, b.z, dot); dot = fmaf(a.w, b.w, dot);
        sx  = fmaf(a.x, a.x, sx);  sx  = fmaf(a.y, a.y, sx);
        sx  = fmaf(a.z, a.z, sx);  sx  = fmaf(a.w, a.w, sx);
        sy  = fmaf(b.x, b.x, sy);  sy  = fmaf(b.y, b.y, sy);
        sy  = fmaf(b.z, b.z, sy);  sy  = fmaf(b.w, b.w, sy);
    }

    // Warp tree reduce (deterministic order)
    #pragma unroll
    for (int o = 16; o > 0; o >>= 1) {
        dot += __shfl_xor_sync(0xFFFFFFFFu, dot, o);
        sx  += __shfl_xor_sync(0xFFFFFFFFu, sx,  o);
        sy  += __shfl_xor_sync(0xFFFFFFFFu, sy,  o);
    }

    __shared__ float s[WARPS_PER_BLOCK][3];
    if (lane == 0) {
        s[warp][0] = dot * dot;   // per-row contribution is dot^2
        s[warp][1] = sx;
        s[warp][2] = sy;
    }
    __syncthreads();

    if (threadIdx.x < 3) {
        float acc = 0.f;
        #pragma unroll
        for (int w = 0; w < WARPS_PER_BLOCK; ++w) acc += s[w][threadIdx.x];
        g_partials[(size_t)threadIdx.x * NBLOCKS + blockIdx.x] = acc;
    }
}

__global__ __launch_bounds__(1024)
void finalize_kernel(float* __restrict__ out) {
    const int tid  = threadIdx.x;
    const int warp = tid >> 5;
    const int lane = tid & 31;
    const float* __restrict__ p = g_partials;

    float a0 = 0.f, a1 = 0.f, a2 = 0.f;
    for (int i = tid; i < NBLOCKS; i += 1024) {
        a0 += p[i];
        a1 += p[i + NBLOCKS];
        a2 += p[i + 2 * NBLOCKS];
    }
    #pragma unroll
    for (int o = 16; o > 0; o >>= 1) {
        a0 += __shfl_xor_sync(0xFFFFFFFFu, a0, o);
        a1 += __shfl_xor_sync(0xFFFFFFFFu, a1, o);
        a2 += __shfl_xor_sync(0xFFFFFFFFu, a2, o);
    }

    __shared__ float s0[32], s1[32], s2[32];
    if (lane == 0) { s0[warp] = a0; s1[warp] = a1; s2[warp] = a2; }
    __syncthreads();

    if (warp == 0) {
        float v0 = s0[lane], v1 = s1[lane], v2 = s2[lane];
        #pragma unroll
        for (int o = 16; o > 0; o >>= 1) {
            v0 += __shfl_xor_sync(0xFFFFFFFFu, v0, o);
            v1 += __shfl_xor_sync(0xFFFFFFFFu, v1, o);
            v2 += __shfl_xor_sync(0xFFFFFFFFu, v2, o);
        }
        if (lane == 0) {
            // mean((dot / (||x||*||y||) * RAD2DEG)^2)
            //   = RAD2DEG^2 * sum(dot^2) / (N * Sx * Sy)
            double sum_dot2 = (double)v0;
            double sxx = (double)v1;
            double syy = (double)v2;
            double r = (RAD2DEG * RAD2DEG) * sum_dot2 / (sxx * syy * (double)NROWS);
            out[0] = (float)r;
        }
    }
}

extern "C" void kernel_launch(void* const* d_in, const int* in_sizes, int n_in,
                              void* d_out, int out_size) {
    const float* x = (const float*)d_in[0];
    const float* y = (const float*)d_in[1];
    float* out = (float*)d_out;

    rowdot_kernel<<<NBLOCKS, 256>>>(x, y);
    finalize_kernel<<<1, 1024>>>(out);
}